// round 3
// baseline (speedup 1.0000x reference)
#include <cuda_runtime.h>
#include <stdint.h>

// Fused: each block loads |diag(W)| into shared (L2-hit after wave 1),
// then streams x -> out with float4, streaming cache hints, unroll-4 MLP.
// Exact-trip-count path for n4 divisible by gridDim*blockDim.
__global__ void diag_mul_fused_kernel(const float4* __restrict__ x4,
                                      const float* __restrict__ W,
                                      float4* __restrict__ out4,
                                      long n4, int D) {
    __shared__ float s_d[1024];
    // 256 threads x 4 = 1024 diagonal elements; stride D+1 in W.
    #pragma unroll
    for (int j = threadIdx.x; j < 1024; j += 256) {
        s_d[j] = fabsf(__ldg(&W[(size_t)j * (D + 1)]));
    }
    __syncthreads();

    const float4* s_d4 = reinterpret_cast<const float4*>(s_d);

    const long stride = (long)gridDim.x * blockDim.x;      // 2^19 for 2048x256
    long i = (long)blockIdx.x * blockDim.x + threadIdx.x;
    const long iters = n4 / stride;                        // exact (32) for this shape
    const long main_end = iters * stride;

    // Main loop: unroll 4 -> 4 independent LDG.128 in flight per body.
    long it = 0;
    for (; it + 4 <= iters; it += 4) {
        float4 v0 = __ldcs(&x4[i]);
        float4 v1 = __ldcs(&x4[i + stride]);
        float4 v2 = __ldcs(&x4[i + 2 * stride]);
        float4 v3 = __ldcs(&x4[i + 3 * stride]);
        float4 d = s_d4[(int)(i & 255)];   // stride is a multiple of 256 -> same d each iter
        v0.x *= d.x; v0.y *= d.y; v0.z *= d.z; v0.w *= d.w;
        v1.x *= d.x; v1.y *= d.y; v1.z *= d.z; v1.w *= d.w;
        v2.x *= d.x; v2.y *= d.y; v2.z *= d.z; v2.w *= d.w;
        v3.x *= d.x; v3.y *= d.y; v3.z *= d.z; v3.w *= d.w;
        __stcs(&out4[i], v0);
        __stcs(&out4[i + stride], v1);
        __stcs(&out4[i + 2 * stride], v2);
        __stcs(&out4[i + 3 * stride], v3);
        i += 4 * stride;
    }
    // Remainder of exact iterations (if iters % 4 != 0)
    for (; it < iters; ++it) {
        float4 v = __ldcs(&x4[i]);
        float4 d = s_d4[(int)(i & 255)];
        v.x *= d.x; v.y *= d.y; v.z *= d.z; v.w *= d.w;
        __stcs(&out4[i], v);
        i += stride;
    }
    // Tail (n4 not divisible by stride) — not hit for this shape, kept for safety.
    for (long t = main_end + (long)blockIdx.x * blockDim.x + threadIdx.x;
         t < n4; t += stride) {
        float4 v = __ldcs(&x4[t]);
        float4 d = s_d4[(int)(t & 255)];
        v.x *= d.x; v.y *= d.y; v.z *= d.z; v.w *= d.w;
        __stcs(&out4[t], v);
    }
}

extern "C" void kernel_launch(void* const* d_in, const int* in_sizes, int n_in,
                              void* d_out, int out_size) {
    const float* x = (const float*)d_in[0];
    const float* W = (const float*)d_in[1];
    float* out = (float*)d_out;

    const int D = 1024;
    const long n4 = (long)out_size / 4;   // 2^24 for 65536x1024

    // 2048 blocks x 256 threads = 2^19 threads -> exactly 32 float4/thread.
    diag_mul_fused_kernel<<<2048, 256>>>(
        reinterpret_cast<const float4*>(x), W,
        reinterpret_cast<float4*>(out), n4, D);
}

// round 4
// speedup vs baseline: 1.0989x; 1.0989x over previous
#include <cuda_runtime.h>
#include <stdint.h>

// out[b,d] = x[b,d] * |W[d,d]|, fused single kernel.
// Grid-stride with blockDim=256 and D/4=256 float4 column groups:
// (i mod 256) == threadIdx.x for all iterations, so each thread's diag
// float4 is loop-invariant -> load it once, no shared memory needed.
__global__ void __launch_bounds__(256) diag_mul_kernel(
    const float4* __restrict__ x4,
    const float* __restrict__ W,
    float4* __restrict__ out4,
    long n4, int D) {
    // This thread's 4 diagonal elements: columns 4*tid .. 4*tid+3.
    int c = threadIdx.x * 4;
    float4 d;
    d.x = fabsf(__ldg(&W[(size_t)(c + 0) * (D + 1)]));
    d.y = fabsf(__ldg(&W[(size_t)(c + 1) * (D + 1)]));
    d.z = fabsf(__ldg(&W[(size_t)(c + 2) * (D + 1)]));
    d.w = fabsf(__ldg(&W[(size_t)(c + 3) * (D + 1)]));

    const long stride = (long)gridDim.x * blockDim.x;  // multiple of 256
    for (long i = (long)blockIdx.x * blockDim.x + threadIdx.x; i < n4; i += stride) {
        float4 v = x4[i];
        v.x *= d.x;
        v.y *= d.y;
        v.z *= d.z;
        v.w *= d.w;
        out4[i] = v;
    }
}

extern "C" void kernel_launch(void* const* d_in, const int* in_sizes, int n_in,
                              void* d_out, int out_size) {
    const float* x = (const float*)d_in[0];
    const float* W = (const float*)d_in[1];
    float* out = (float*)d_out;

    const int D = 1024;
    const long n4 = (long)out_size / 4;  // 2^24 for 65536x1024

    // 8 blocks/SM x 8 warps = 64 warps/SM (full occupancy at 32 regs).
    int blocks = 148 * 16;  // 2368, grid-stride covers n4
    diag_mul_kernel<<<blocks, 256>>>(
        reinterpret_cast<const float4*>(x), W,
        reinterpret_cast<float4*>(out), n4, D);
}

// round 5
// speedup vs baseline: 1.1171x; 1.0166x over previous
#include <cuda_runtime.h>
#include <stdint.h>

// out[b,d] = x[b,d] * |W[d,d]|, fused single kernel.
// Grid-stride with blockDim=256 and D/4=256 float4 column groups:
// (i mod 256) == threadIdx.x for all iterations, so each thread's diag
// float4 is loop-invariant -> load it once.
// Hot loop uses streaming cache hints (__ldcs/__stcs): x and out have zero
// reuse, so mark both evict-first to keep L2 clean. No extra registers.
__global__ void __launch_bounds__(256) diag_mul_kernel(
    const float4* __restrict__ x4,
    const float* __restrict__ W,
    float4* __restrict__ out4,
    long n4, int D) {
    // This thread's 4 diagonal elements: columns 4*tid .. 4*tid+3.
    int c = threadIdx.x * 4;
    float4 d;
    d.x = fabsf(__ldg(&W[(size_t)(c + 0) * (D + 1)]));
    d.y = fabsf(__ldg(&W[(size_t)(c + 1) * (D + 1)]));
    d.z = fabsf(__ldg(&W[(size_t)(c + 2) * (D + 1)]));
    d.w = fabsf(__ldg(&W[(size_t)(c + 3) * (D + 1)]));

    const long stride = (long)gridDim.x * blockDim.x;  // multiple of 256
    for (long i = (long)blockIdx.x * blockDim.x + threadIdx.x; i < n4; i += stride) {
        float4 v = __ldcs(&x4[i]);
        v.x *= d.x;
        v.y *= d.y;
        v.z *= d.z;
        v.w *= d.w;
        __stcs(&out4[i], v);
    }
}

extern "C" void kernel_launch(void* const* d_in, const int* in_sizes, int n_in,
                              void* d_out, int out_size) {
    const float* x = (const float*)d_in[0];
    const float* W = (const float*)d_in[1];
    float* out = (float*)d_out;

    const int D = 1024;
    const long n4 = (long)out_size / 4;  // 2^24 for 65536x1024

    int blocks = 148 * 16;  // 2368; 8 resident blocks/SM at 32 regs, grid-stride covers rest
    diag_mul_kernel<<<blocks, 256>>>(
        reinterpret_cast<const float4*>(x), W,
        reinterpret_cast<float4*>(out), n4, D);
}